// round 5
// baseline (speedup 1.0000x reference)
#include <cuda_runtime.h>
#include <cuda_bf16.h>

// ---- constants from the reference ----
#define ELE_FACTOR 332.0637f
#define EWALD_F    1.12837917f
#define EWALD_P    0.3275911f
#define EA0        0.254829592f
#define EA1       -0.284496736f
#define EA2        1.421413741f
#define EA3       -1.453152027f
#define EA4        1.061405429f
#define COUL_BETA  18.7f
#define COUL_R0    2.2f
#define G_EWALD    0.3f
// 4.5^6
#define R6_SHIFT   8303.765625f
// 1 / DISP_CUTOFF^6 = 1/10^6
#define INV_CUT6   1.0e-6f

#define MAX_ATOMS 200000

// scratch: packed per-atom data (charge, c6, r0, pad). 3.2 MB, L2-resident.
__device__ float4 g_atoms[MAX_ATOMS];

__global__ void pack_atoms_kernel(const float* __restrict__ q,
                                  const float* __restrict__ c6,
                                  const float* __restrict__ r0,
                                  int n) {
    int i = blockIdx.x * blockDim.x + threadIdx.x;
    if (i < n) {
        g_atoms[i] = make_float4(q[i], c6[i], r0[i], 0.0f);
    }
}

__global__ void __launch_bounds__(256)
bamboo_edge_kernel(const int*   __restrict__ row,
                   const int*   __restrict__ col,
                   const float* __restrict__ dij,
                   float*       __restrict__ out,
                   int E) {
    int i = blockIdx.x * blockDim.x + threadIdx.x;
    if (i >= E) return;

    int ri = row[i];
    int ci = col[i];

    float4 A = __ldg(&g_atoms[ri]);   // (q, c6, r0)
    float4 B = __ldg(&g_atoms[ci]);

    float dx = dij[3 * i + 0];
    float dy = dij[3 * i + 1];
    float dz = dij[3 * i + 2];

    float r2     = dx * dx + dy * dy + dz * dz;
    float rinv   = rsqrtf(r2);
    float rij    = r2 * rinv;
    float inv_r2 = rinv * rinv;

    // ---------------- Coulomb ----------------
    float prefactor = ELE_FACTOR * A.x * B.x * rinv;

    // x = beta/r0 * (rij - r0); shared by sigmoid and softplus.
    float x  = (COUL_BETA / COUL_R0) * (rij - COUL_R0);
    float ex = __expf(-fabsf(x));          // in (0, 1]
    float inv1pex = __fdividef(1.0f, 1.0f + ex);
    float damp = (x >= 0.0f) ? inv1pex : (ex * inv1pex);      // sigmoid(x), stable
    // softplus(x)/beta, stable: (max(x,0) + log(1 + e^{-|x|}))/beta
    float sp = (fmaxf(x, 0.0f) + __logf(1.0f + ex)) * (1.0f / COUL_BETA);
    float s  = rij * (1.0f / COUL_R0) * __fdividef(1.0f, 1.0f + sp);

    // Ewald short-range erfc correction
    float grij  = G_EWALD * rij;
    float expm2 = __expf(-grij * grij);
    float t     = __fdividef(1.0f, 1.0f + EWALD_P * grij);
    float erfc  = t * (EA0 + t * (EA1 + t * (EA2 + t * (EA3 + t * EA4)))) * expm2;

    float ecoul = prefactor * (s + (erfc - 1.0f));
    float fcoul = prefactor * (damp * s * s + erfc + EWALD_F * grij * expm2 - 1.0f);
    float fc    = fcoul * inv_r2;

    // ---------------- Dispersion (D3-CSO) ----------------
    float c6ij  = sqrtf(A.y * B.y);
    float r0ij  = 0.5f * (A.z + B.z);
    float r6    = r2 * r2 * r2 + R6_SHIFT;
    float inv_r6 = __fdividef(1.0f, r6);
    float e      = __expf(rij - 2.5f * r0ij);
    float inv1pe = __fdividef(1.0f, 1.0f + e);
    float cso    = 0.85f + 0.82f * inv1pe;

    float edisp = -c6ij * inv_r6 * cso + c6ij * INV_CUT6;
    float r5    = r2 * r2 * rij;
    float fdisp = -6.0f * c6ij * r5 * inv_r6 * inv_r6 * cso
                  - c6ij * inv_r6 * (0.82f * e * inv1pe * inv1pe);
    float fd    = fdisp * rinv;

    // ---------------- outputs ----------------
    // layout: [ecoul E | coul_fij 3E | edisp E | disp_fij 3E]
    out[i] = ecoul;
    float* cf = out + E + 3 * i;
    cf[0] = dx * fc;
    cf[1] = dy * fc;
    cf[2] = dz * fc;
    out[4 * E + i] = edisp;
    float* df = out + 5 * E + 3 * i;
    df[0] = dx * fd;
    df[1] = dy * fd;
    df[2] = dz * fd;
}

extern "C" void kernel_launch(void* const* d_in, const int* in_sizes, int n_in,
                              void* d_out, int out_size) {
    const int*   row    = (const int*)d_in[0];
    const int*   col    = (const int*)d_in[1];
    const float* dij    = (const float*)d_in[2];
    const float* charge = (const float*)d_in[3];
    const float* c6     = (const float*)d_in[4];
    const float* r0     = (const float*)d_in[5];
    float* out = (float*)d_out;

    int E = in_sizes[0];
    int N = in_sizes[3];

    int tpb = 256;
    pack_atoms_kernel<<<(N + tpb - 1) / tpb, tpb>>>(charge, c6, r0, N);
    bamboo_edge_kernel<<<(E + tpb - 1) / tpb, tpb>>>(row, col, dij, out, E);
}